// round 1
// baseline (speedup 1.0000x reference)
#include <cuda_runtime.h>
#include <math.h>
#include <stdint.h>

#define BB 4
#define C 96
#define H 128
#define W 128
#define HW (H*W)          // 16384
#define KKc 9
#define CK (C*KKc)        // 864
#define NPIX (BB*HW)      // 65536 per channel

// ---------------- device scratch (no allocations allowed) ----------------
__device__ float g_col [ (size_t)BB * CK * HW ];   // 226.5 MB im2col / deform-col
__device__ float g_om  [ (size_t)BB * 27 * HW ];   // offset+mask conv raw output
__device__ float g_w27 [ 27 * CK ];                // concatenated offset|mask weights
__device__ float g_conv[ (size_t)BB * C * HW ];    // deform-conv output
__device__ float g_act [ (size_t)BB * C * HW ];    // post BN+leakyrelu
__device__ float g_stats[ 2 * C ];                 // mean | rstd

// ---------------- small helpers ----------------
__global__ void concat27_kernel(const float* __restrict__ offw,
                                const float* __restrict__ modw,
                                float* __restrict__ dst) {
    int i = blockIdx.x * blockDim.x + threadIdx.x;
    if (i >= 27 * CK) return;
    dst[i] = (i < 18 * CK) ? offw[i] : modw[i - 18 * CK];
}

// identity im2col: col[b][c*9+k][hw] = x[b][c][h+ky-1][w+kx-1] (zero padded)
__global__ void build_patch_kernel(const float* __restrict__ in,
                                   float* __restrict__ col) {
    int idx = blockIdx.x * blockDim.x + threadIdx.x;   // over BB*KK*HW
    if (idx >= BB * KKc * HW) return;
    int hw = idx % HW;
    int t  = idx / HW;
    int k  = t % KKc;
    int b  = t / KKc;
    int h = hw / W, w = hw % W;
    int yy = h + k / 3 - 1;
    int xx = w + k % 3 - 1;
    bool ok = (yy >= 0 && yy < H && xx >= 0 && xx < W);
    const float* p = in + (size_t)b * C * HW + yy * W + xx;
    float* o = col + ((size_t)b * CK + k) * HW + hw;
    #pragma unroll 4
    for (int c = 0; c < C; c++) {
        float v = 0.f;
        if (ok) v = p[0];
        *o = v;
        p += HW;
        o += (size_t)KKc * HW;
    }
}

// deformable im2col with mask folded in:
// col[b][c*9+k][hw] = bilinear(x[b][c], py, px) * mask
__global__ void deform_col_kernel(const float* __restrict__ in,
                                  const float* __restrict__ om,
                                  const float* __restrict__ off_b,
                                  const float* __restrict__ mod_b,
                                  float* __restrict__ col) {
    int idx = blockIdx.x * blockDim.x + threadIdx.x;   // over BB*KK*HW
    if (idx >= BB * KKc * HW) return;
    int hw = idx % HW;
    int t  = idx / HW;
    int k  = t % KKc;
    int b  = t / KKc;
    int h = hw / W, w = hw % W;

    const float* omb = om + (size_t)b * 27 * HW + hw;
    float offy = omb[(size_t)(2 * k    ) * HW] + off_b[2 * k];
    float offx = omb[(size_t)(2 * k + 1) * HW] + off_b[2 * k + 1];
    float mraw = omb[(size_t)(18 + k   ) * HW] + mod_b[k];
    float mval = 2.f / (1.f + expf(-mraw));

    float py = (float)h - 1.f + (float)(k / 3) + offy;
    float px = (float)w - 1.f + (float)(k % 3) + offx;
    float y0f = floorf(py), x0f = floorf(px);
    float dy = py - y0f, dx = px - x0f;
    int y0 = (int)y0f, x0 = (int)x0f;
    int y1 = y0 + 1,   x1 = x0 + 1;

    float v00 = (y0 >= 0 && y0 < H && x0 >= 0 && x0 < W) ? 1.f : 0.f;
    float v01 = (y0 >= 0 && y0 < H && x1 >= 0 && x1 < W) ? 1.f : 0.f;
    float v10 = (y1 >= 0 && y1 < H && x0 >= 0 && x0 < W) ? 1.f : 0.f;
    float v11 = (y1 >= 0 && y1 < H && x1 >= 0 && x1 < W) ? 1.f : 0.f;

    int y0c = min(max(y0, 0), H - 1), y1c = min(max(y1, 0), H - 1);
    int x0c = min(max(x0, 0), W - 1), x1c = min(max(x1, 0), W - 1);

    float w00 = (1.f - dy) * (1.f - dx) * mval * v00;
    float w01 = (1.f - dy) * dx         * mval * v01;
    float w10 = dy         * (1.f - dx) * mval * v10;
    float w11 = dy         * dx         * mval * v11;

    int i00 = y0c * W + x0c, i01 = y0c * W + x1c;
    int i10 = y1c * W + x0c, i11 = y1c * W + x1c;

    const float* p = in + (size_t)b * C * HW;
    float* o = col + ((size_t)b * CK + k) * HW + hw;
    #pragma unroll 4
    for (int c = 0; c < C; c++) {
        float v = p[i00] * w00 + p[i01] * w01 + p[i10] * w10 + p[i11] * w11;
        *o = v;
        p += HW;
        o += (size_t)KKc * HW;
    }
}

// ---------------- SGEMM: Out[b][m][hw] = sum_k A[m][k] * Bmat[b][k][hw] ----
// Block tile: BM x 128, K-tile 16, 256 threads, micro tile TM x 8.
template<int BM, int TM>
__global__ void sgemm_kernel(const float* __restrict__ A,
                             const float* __restrict__ Bmat,
                             float* __restrict__ Out,
                             int M) {
    constexpr int BN = 128;
    constexpr int BK = 16;
    __shared__ float As[BK][BM + 1];
    __shared__ float Bs[BK][BN];

    int tid = threadIdx.x;                 // 256 threads
    int b   = blockIdx.y;
    int n0  = blockIdx.x * BN;
    int tx  = tid & 15;                    // 16 n-groups of 8
    int ty  = tid >> 4;                    // 16 m-groups of TM

    const float* Bb = Bmat + (size_t)b * CK * HW;

    float acc[TM][8];
    #pragma unroll
    for (int i = 0; i < TM; i++)
        #pragma unroll
        for (int j = 0; j < 8; j++) acc[i][j] = 0.f;

    int br = tid >> 5;           // 0..7
    int bc = (tid & 31) * 4;     // 0..124

    for (int k0 = 0; k0 < CK; k0 += BK) {
        // A tile (BM x 16)
        #pragma unroll
        for (int i = 0; i < (BM * BK) / 256; i++) {
            int e = tid + i * 256;
            int m = e >> 4;
            int k = e & 15;
            As[k][m] = (m < M) ? A[m * CK + k0 + k] : 0.f;
        }
        // B tile (16 x 128), fully coalesced float4
        #pragma unroll
        for (int i = 0; i < 2; i++) {
            float4 v = *reinterpret_cast<const float4*>(
                Bb + (size_t)(k0 + br + 8 * i) * HW + n0 + bc);
            *reinterpret_cast<float4*>(&Bs[br + 8 * i][bc]) = v;
        }
        __syncthreads();

        #pragma unroll
        for (int k = 0; k < BK; k++) {
            float a[TM];
            #pragma unroll
            for (int i = 0; i < TM; i++) a[i] = As[k][ty * TM + i];
            float4 b0 = *reinterpret_cast<const float4*>(&Bs[k][tx * 8]);
            float4 b1 = *reinterpret_cast<const float4*>(&Bs[k][tx * 8 + 4]);
            float bv[8] = {b0.x, b0.y, b0.z, b0.w, b1.x, b1.y, b1.z, b1.w};
            #pragma unroll
            for (int i = 0; i < TM; i++)
                #pragma unroll
                for (int j = 0; j < 8; j++)
                    acc[i][j] += a[i] * bv[j];
        }
        __syncthreads();
    }

    #pragma unroll
    for (int i = 0; i < TM; i++) {
        int m = ty * TM + i;
        if (m < M) {
            float* op = Out + ((size_t)b * M + m) * HW + n0 + tx * 8;
            float4 o0 = make_float4(acc[i][0], acc[i][1], acc[i][2], acc[i][3]);
            float4 o1 = make_float4(acc[i][4], acc[i][5], acc[i][6], acc[i][7]);
            *reinterpret_cast<float4*>(op)     = o0;
            *reinterpret_cast<float4*>(op + 4) = o1;
        }
    }
}

// ---------------- batch norm ----------------
__global__ void bn_stats_kernel(const float* __restrict__ X,
                                float* __restrict__ stats) {
    int c = blockIdx.x;
    float s = 0.f, s2 = 0.f;
    for (int i = threadIdx.x; i < NPIX; i += blockDim.x) {
        int b  = i >> 14;          // HW = 2^14
        int hw = i & (HW - 1);
        float v = X[((size_t)b * C + c) * HW + hw];
        s  += v;
        s2 += v * v;
    }
    __shared__ float sh[256], sh2[256];
    sh[threadIdx.x] = s; sh2[threadIdx.x] = s2;
    __syncthreads();
    for (int st = 128; st > 0; st >>= 1) {
        if (threadIdx.x < st) {
            sh[threadIdx.x]  += sh[threadIdx.x + st];
            sh2[threadIdx.x] += sh2[threadIdx.x + st];
        }
        __syncthreads();
    }
    if (threadIdx.x == 0) {
        float inv = 1.f / (float)NPIX;
        float mean = sh[0] * inv;
        float var  = sh2[0] * inv - mean * mean;
        stats[c]     = mean;
        stats[C + c] = rsqrtf(var + 1e-5f);
    }
}

__global__ void bn_lrelu_kernel(const float* __restrict__ X,
                                const float* __restrict__ gam,
                                const float* __restrict__ bet,
                                const float* __restrict__ stats,
                                float* __restrict__ O) {
    int idx = blockIdx.x * blockDim.x + threadIdx.x;
    if (idx >= BB * C * HW) return;
    int c = (idx / HW) % C;
    float v = (X[idx] - stats[c]) * stats[C + c] * gam[c] + bet[c];
    O[idx] = v >= 0.f ? v : 0.1f * v;
}

__global__ void bn_add_kernel(const float* __restrict__ Xres,
                              const float* __restrict__ Hc,
                              const float* __restrict__ gam,
                              const float* __restrict__ bet,
                              const float* __restrict__ stats,
                              float* __restrict__ O) {
    int idx = blockIdx.x * blockDim.x + threadIdx.x;
    if (idx >= BB * C * HW) return;
    int c = (idx / HW) % C;
    float v = (Hc[idx] - stats[c]) * stats[C + c] * gam[c] + bet[c];
    O[idx] = Xres[idx] + v;
}

// ---------------- launch ----------------
extern "C" void kernel_launch(void* const* d_in, const int* in_sizes, int n_in,
                              void* d_out, int out_size) {
    const float* x        = (const float*)d_in[0];
    const float* d1_off_w = (const float*)d_in[1];
    const float* d1_off_b = (const float*)d_in[2];
    const float* d1_mod_w = (const float*)d_in[3];
    const float* d1_mod_b = (const float*)d_in[4];
    const float* d1_w     = (const float*)d_in[5];
    const float* d2_off_w = (const float*)d_in[6];
    const float* d2_off_b = (const float*)d_in[7];
    const float* d2_mod_w = (const float*)d_in[8];
    const float* d2_mod_b = (const float*)d_in[9];
    const float* d2_w     = (const float*)d_in[10];
    const float* bn_g     = (const float*)d_in[11];
    const float* bn_b     = (const float*)d_in[12];
    float* out = (float*)d_out;

    float *p_col, *p_om, *p_w27, *p_conv, *p_act, *p_stats;
    cudaGetSymbolAddress((void**)&p_col,   g_col);
    cudaGetSymbolAddress((void**)&p_om,    g_om);
    cudaGetSymbolAddress((void**)&p_w27,   g_w27);
    cudaGetSymbolAddress((void**)&p_conv,  g_conv);
    cudaGetSymbolAddress((void**)&p_act,   g_act);
    cudaGetSymbolAddress((void**)&p_stats, g_stats);

    const int NT = 256;
    const int nCol  = BB * KKc * HW;                 // 589824
    const int nElem = BB * C * HW;                   // 6291456
    dim3 gemm_grid(HW / 128, BB);

    // ---------- layer 1 ----------
    concat27_kernel<<<(27 * CK + NT - 1) / NT, NT>>>(d1_off_w, d1_mod_w, p_w27);
    build_patch_kernel<<<(nCol + NT - 1) / NT, NT>>>(x, p_col);
    sgemm_kernel<32, 2><<<gemm_grid, NT>>>(p_w27, p_col, p_om, 27);
    deform_col_kernel<<<(nCol + NT - 1) / NT, NT>>>(x, p_om, d1_off_b, d1_mod_b, p_col);
    sgemm_kernel<96, 6><<<gemm_grid, NT>>>(d1_w, p_col, p_conv, C);
    bn_stats_kernel<<<C, NT>>>(p_conv, p_stats);
    bn_lrelu_kernel<<<(nElem + NT - 1) / NT, NT>>>(p_conv, bn_g, bn_b, p_stats, p_act);

    // ---------- layer 2 ----------
    concat27_kernel<<<(27 * CK + NT - 1) / NT, NT>>>(d2_off_w, d2_mod_w, p_w27);
    build_patch_kernel<<<(nCol + NT - 1) / NT, NT>>>(p_act, p_col);
    sgemm_kernel<32, 2><<<gemm_grid, NT>>>(p_w27, p_col, p_om, 27);
    deform_col_kernel<<<(nCol + NT - 1) / NT, NT>>>(p_act, p_om, d2_off_b, d2_mod_b, p_col);
    sgemm_kernel<96, 6><<<gemm_grid, NT>>>(d2_w, p_col, p_conv, C);
    bn_stats_kernel<<<C, NT>>>(p_conv, p_stats);
    bn_add_kernel<<<(nElem + NT - 1) / NT, NT>>>(x, p_conv, bn_g, bn_b, p_stats, out);
}